// round 16
// baseline (speedup 1.0000x reference)
#include <cuda_runtime.h>
#include <math.h>

#define NIN 49

typedef unsigned long long u64;

// ---- f32x2 packed helpers (sm_100+) ----
__device__ __forceinline__ u64 pk2(float lo, float hi) {
    u64 r; asm("mov.b64 %0, {%1,%2};" : "=l"(r) : "f"(lo), "f"(hi)); return r;
}
__device__ __forceinline__ void upk2(float& lo, float& hi, u64 v) {
    asm("mov.b64 {%0,%1}, %2;" : "=f"(lo), "=f"(hi) : "l"(v));
}
__device__ __forceinline__ u64 fma2(u64 a, u64 b, u64 c) {
    u64 d; asm("fma.rn.f32x2 %0, %1, %2, %3;" : "=l"(d) : "l"(a), "l"(b), "l"(c)); return d;
}
__device__ __forceinline__ u64 mul2(u64 a, u64 b) {
    u64 d; asm("mul.rn.f32x2 %0, %1, %2;" : "=l"(d) : "l"(a), "l"(b)); return d;
}

// Two warps (64 threads) = one sample. Amp index z (10 bits):
//   z9 = warp, z[8:4] = lane, z[3:1] = slot k (8 u64 SoA pairs), z0 = packed half.
// Qubit q acts on bit 9-q:
//   q0 -> warp bit (cross-warp via SMEM), q1..q5 -> lane bits (u64 shfl butterfly),
//   q6..q8 -> slot bits (pure f32x2 FMA), q9 -> packed bit (vectorized w/ half-swap).
// Layer 0 (product state) is constructed directly with its CNOT permutation folded in.
// BOTH layers 1 and 2 use the gauge form [[P,-C],[conj(C),P]] with P real (12 FMA/pair):
//   layer 1: RIGHT gauge U' = U*H, H=diag(e^{-i psi},e^{+i psi}), psi=arg(A), C=B*A/|A|.
//     Compensation H^{-1} acts on layer-1's INPUT basis and is merged EXACTLY into the
//     layer-0 construction (thread seed + amp-coordinate doubling tree with
//     branch-constant combined factors F_j[prev][bit] = f_j(bit^prev)*c_j(bit)).
//   layer 2: LEFT gauge diag*U, C = B*conj(A)/|A|; residual per-row phases are
//     unobservable in the final |amp|^2 readout.
// The LAST layer's CNOT-chain permutation is folded into the readout weights.
__global__ void __launch_bounds__(64)
qcirc_kernel(const float* __restrict__ x,
             const float* __restrict__ theta,
             const float* __restrict__ alpha_raw,
             const float* __restrict__ beta_raw,
             const float* __restrict__ head_w,
             const float* __restrict__ head_b,
             const float* __restrict__ logit_scale,
             float* __restrict__ out, int batch)
{
    __shared__ u64 xch[16][64];     // [j<8]=re slot j, [8+j]=im slot j; col = thread
    __shared__ float red[2];

    const unsigned FULL = 0xFFFFFFFFu;
    const int t    = threadIdx.x;
    const int lane = t & 31;
    const int w    = t >> 5;
    const int b    = blockIdx.x;
    if (b >= batch) return;

    // ---- per-lane fused gate coefficients (identical in both warps) ----
    // U = RX(theta)*RY(enc) = [[A,-B],[conj(B),conj(A)]]
    // A = cx*cy - i*sx*sy,  B = cx*sy + i*sx*cy
    float myAx, myAy, myBx, myBy;   // lanes 0..9: layer-0 product factors (pure)
    float myP, myCx, myCy;          // lanes 10..29: gauge coefficients
    float myEx, myEy;               // e^{i psi} = A/|A| (used from lanes 10..19)
    {
        const int g  = (lane < 30) ? lane : 0;
        const float th = theta[g];
        const float ar = alpha_raw[g];
        const float br = beta_raw[g];
        const float xv = x[b * NIN + g];
        float sp    = fmaxf(ar, 0.0f) + log1pf(expf(-fabsf(ar)));   // softplus
        float alpha = sp + 1e-6f;
        float beta  = tanhf(br);
        const float HALF_PI = 1.5707963267948966f;                  // 0.5 * pi
        float hy = HALF_PI * (alpha * xv + beta);
        float sy, cy; sincosf(hy, &sy, &cy);
        float sx, cx; sincosf(0.5f * th, &sx, &cx);
        myAx = cx * cy;
        myAy = -sx * sy;
        myBx = cx * sy;
        myBy = sx * cy;
        const float nA = fmaxf(myAx * myAx + myAy * myAy, 1e-28f);
        const float ri = rsqrtf(nA);
        myP  = nA * ri;
        // C = B * (Ax + i*s*Ay) * ri :  s=+1 (layer-1 lanes, right gauge, uses A)
        //                               s=-1 (layer-2 lanes, left gauge, uses conj A)
        const float s   = (lane >= 10 && lane < 20) ? 1.0f : -1.0f;
        const float sAy = s * myAy;
        myCx = (myBx * myAx - myBy * sAy) * ri;
        myCy = (myBy * myAx + myBx * sAy) * ri;
        myEx = myAx * ri;
        myEy = myAy * ri;
    }

    const int l4 = (lane >> 4) & 1, l3 = (lane >> 3) & 1, l2 = (lane >> 2) & 1,
              l1 = (lane >> 1) & 1, l0 = lane & 1;

    // =====================================================================
    // Layer 0 + its CNOT chain + layer-1 gauge compensation, folded:
    //   amp[y] = comp(y) * prod_q f_q(bit_{9-q}(y ^ (y>>1)))
    //   f_q(0) = (Ax,Ay);  f_q(1) = (Bx,-By);  c_q(b) = e^{i psi_q (1-2b)}
    // permuted bits: q0<-w, q1<-l4^w, q2<-l3^l4, q3<-l2^l3, q4<-l1^l2, q5<-l0^l1,
    //   q6<-k2^l0 (l0 folded into factor swap), q7<-k1^k2, q8<-k0^k1, q9<-h^k0
    // direct bits (compensation): q0<-w, q1<-l4 .. q5<-l0, q6<-k2, q7<-k1,
    //   q8<-k0, q9<-h
    // =====================================================================
    u64 srp[8], sip[8];
    {
        const int gb[6] = { w, l4 ^ w, l3 ^ l4, l2 ^ l3, l1 ^ l2, l0 ^ l1 };
        const int cb[6] = { w, l4, l3, l2, l1, l0 };

        // thread seed (qubits 0..5): gate factor at permuted bit x comp at direct bit
        float lfr, lfi;
        {
            float Ax = __shfl_sync(FULL, myAx, 0);
            float Ay = __shfl_sync(FULL, myAy, 0);
            float Bx = __shfl_sync(FULL, myBx, 0);
            float By = __shfl_sync(FULL, myBy, 0);
            lfr = gb[0] ? Bx : Ax;
            lfi = gb[0] ? -By : Ay;
            float ex = __shfl_sync(FULL, myEx, 10);
            float ey = __shfl_sync(FULL, myEy, 10);
            float cey = cb[0] ? -ey : ey;
            float nr = lfr * ex - lfi * cey;
            float ni = lfr * cey + lfi * ex;
            lfr = nr; lfi = ni;
#pragma unroll
            for (int q = 1; q < 6; q++) {
                Ax = __shfl_sync(FULL, myAx, q);
                Ay = __shfl_sync(FULL, myAy, q);
                Bx = __shfl_sync(FULL, myBx, q);
                By = __shfl_sync(FULL, myBy, q);
                const float fr = gb[q] ? Bx : Ax;
                const float fi = gb[q] ? -By : Ay;
                nr = lfr * fr - lfi * fi;
                ni = lfr * fi + lfi * fr;
                lfr = nr; lfi = ni;
                ex = __shfl_sync(FULL, myEx, 10 + q);
                ey = __shfl_sync(FULL, myEy, 10 + q);
                cey = cb[q] ? -ey : ey;
                nr = lfr * ex - lfi * cey;
                ni = lfr * cey + lfi * ex;
                lfr = nr; lfi = ni;
            }
        }

        // combined reg factors: F[j][pb][bit] = f_{6+j}(bit^pb) * c_{6+j}(bit)
        // j=0 (bit3) has no prev bit: only [0][bit] used (f6 pre-swapped by l0).
        float Fr[4][2][2], Fi[4][2][2];
#pragma unroll
        for (int j = 0; j < 4; j++) {
            const int q = 6 + j;
            const float Ax = __shfl_sync(FULL, myAx, q);
            const float Ay = __shfl_sync(FULL, myAy, q);
            const float Bx = __shfl_sync(FULL, myBx, q);
            const float By = __shfl_sync(FULL, myBy, q);
            float f0r, f0i, f1r, f1i;
            if (j == 0) {   // f6'(v) = f6(v ^ l0)
                f0r = l0 ? Bx : Ax;  f0i = l0 ? -By : Ay;
                f1r = l0 ? Ax : Bx;  f1i = l0 ? Ay : -By;
            } else {
                f0r = Ax;  f0i = Ay;
                f1r = Bx;  f1i = -By;
            }
            const float ex = __shfl_sync(FULL, myEx, 16 + j);
            const float ey = __shfl_sync(FULL, myEy, 16 + j);
            // c(0) = (ex, ey); c(1) = (ex, -ey)
            Fr[j][0][0] = f0r * ex - f0i * ey;   Fi[j][0][0] = f0r * ey + f0i * ex;
            Fr[j][0][1] = f1r * ex + f1i * ey;   Fi[j][0][1] = -f1r * ey + f1i * ex;
            Fr[j][1][0] = f1r * ex - f1i * ey;   Fi[j][1][0] = f1r * ey + f1i * ex;
            Fr[j][1][1] = f0r * ex + f0i * ey;   Fi[j][1][1] = -f0r * ey + f0i * ex;
        }

        // doubling tree in amp coordinates a=(k2,k1,k0,h), top-down bit3->bit0.
        float gr[16], gi[16];
        gr[0] = lfr; gi[0] = lfi;
        // bit3 (j=0)
        {
            const float a_ = gr[0], c_ = gi[0];
            gr[8] = a_ * Fr[0][0][1] - c_ * Fi[0][0][1];
            gi[8] = a_ * Fi[0][0][1] + c_ * Fr[0][0][1];
            gr[0] = a_ * Fr[0][0][0] - c_ * Fi[0][0][0];
            gi[0] = a_ * Fi[0][0][0] + c_ * Fr[0][0][0];
        }
        // bit2 (j=1)
#pragma unroll
        for (int c0 = 0; c0 < 16; c0 += 8) {
            const int pb = c0 >> 3;
            const float a_ = gr[c0], c_ = gi[c0];
            gr[c0 + 4] = a_ * Fr[1][pb][1] - c_ * Fi[1][pb][1];
            gi[c0 + 4] = a_ * Fi[1][pb][1] + c_ * Fr[1][pb][1];
            gr[c0]     = a_ * Fr[1][pb][0] - c_ * Fi[1][pb][0];
            gi[c0]     = a_ * Fi[1][pb][0] + c_ * Fr[1][pb][0];
        }
        // bit1 (j=2)
#pragma unroll
        for (int c0 = 0; c0 < 16; c0 += 4) {
            const int pb = (c0 >> 2) & 1;
            const float a_ = gr[c0], c_ = gi[c0];
            gr[c0 + 2] = a_ * Fr[2][pb][1] - c_ * Fi[2][pb][1];
            gi[c0 + 2] = a_ * Fi[2][pb][1] + c_ * Fr[2][pb][1];
            gr[c0]     = a_ * Fr[2][pb][0] - c_ * Fi[2][pb][0];
            gi[c0]     = a_ * Fi[2][pb][0] + c_ * Fr[2][pb][0];
        }
        // bit0 (j=3)
#pragma unroll
        for (int c0 = 0; c0 < 16; c0 += 2) {
            const int pb = (c0 >> 1) & 1;
            const float a_ = gr[c0], c_ = gi[c0];
            gr[c0 + 1] = a_ * Fr[3][pb][1] - c_ * Fi[3][pb][1];
            gi[c0 + 1] = a_ * Fi[3][pb][1] + c_ * Fr[3][pb][1];
            gr[c0]     = a_ * Fr[3][pb][0] - c_ * Fi[3][pb][0];
            gi[c0]     = a_ * Fi[3][pb][0] + c_ * Fr[3][pb][0];
        }

        // pack directly (no renaming: tree already in amp coordinates)
#pragma unroll
        for (int k = 0; k < 8; k++) {
            srp[k] = pk2(gr[2 * k], gr[2 * k + 1]);
            sip[k] = pk2(gi[2 * k], gi[2 * k + 1]);
        }
    }

    // =====================================================================
    // Layers 1 and 2 — identical gauge form [[P,-C],[conj(C),P]], 12 FMA/pair
    // =====================================================================
#pragma unroll 1
    for (int layer = 1; layer < 3; layer++) {
        const int gbase = layer * 10;

        // ---- qubit 0: cross-warp gauge gate via SMEM exchange ----
        {
            __syncthreads();   // prior readers of xch done
#pragma unroll
            for (int j = 0; j < 8; j++) {
                xch[j][t]     = srp[j];
                xch[j + 8][t] = sip[j];
            }
            __syncthreads();

            const float P  = __shfl_sync(FULL, myP,  gbase);
            const float Cx = __shfl_sync(FULL, myCx, gbase);
            const float Cy = __shfl_sync(FULL, myCy, gbase);
            const bool hi = (w != 0);
            const float Dx = hi ? Cx : -Cx;
            const u64 p2   = pk2(P,  P);
            const u64 dx2  = pk2(Dx, Dx);
            const u64 cy2  = pk2(Cy, Cy);
            const u64 ncy2 = pk2(-Cy, -Cy);
            const int pt = t ^ 32;
            u64 prp[8], pip[8];
#pragma unroll
            for (int k = 0; k < 8; k++) {
                prp[k] = xch[k][pt];
                pip[k] = xch[k + 8][pt];
            }
#pragma unroll
            for (int k = 0; k < 8; k++) {
                u64 nr = mul2(p2, srp[k]);
                nr = fma2(dx2, prp[k], nr);
                nr = fma2(cy2, pip[k], nr);
                u64 ni = mul2(p2, sip[k]);
                ni = fma2(dx2, pip[k], ni);
                ni = fma2(ncy2, prp[k], ni);
                srp[k] = nr; sip[k] = ni;
            }
        }

        // ---- qubits 1..5: lane-bit gauge gates, two-phase (u64 shfl, no pack movs) ----
#pragma unroll
        for (int q = 1; q < 6; q++) {
            const int g  = gbase + q;
            const float P  = __shfl_sync(FULL, myP,  g);
            const float Cx = __shfl_sync(FULL, myCx, g);
            const float Cy = __shfl_sync(FULL, myCy, g);
            const int m = 1 << (5 - q);
            const bool hi = (lane & m) != 0;
            const float Dx = hi ? Cx : -Cx;
            const u64 p2   = pk2(P,  P);
            const u64 dx2  = pk2(Dx, Dx);
            const u64 cy2  = pk2(Cy, Cy);
            const u64 ncy2 = pk2(-Cy, -Cy);
            u64 prp[8], pip[8];
#pragma unroll
            for (int k = 0; k < 8; k++) {
                prp[k] = __shfl_xor_sync(FULL, srp[k], m);
                pip[k] = __shfl_xor_sync(FULL, sip[k], m);
            }
#pragma unroll
            for (int k = 0; k < 8; k++) {
                u64 nr = mul2(p2, srp[k]);
                nr = fma2(dx2, prp[k], nr);
                nr = fma2(cy2, pip[k], nr);
                u64 ni = mul2(p2, sip[k]);
                ni = fma2(dx2, pip[k], ni);
                ni = fma2(ncy2, prp[k], ni);
                srp[k] = nr; sip[k] = ni;
            }
        }

        // ---- qubits 6..8: slot-bit gauge gates ----
#pragma unroll
        for (int q = 6; q < 9; q++) {
            const int g  = gbase + q;
            const float P  = __shfl_sync(FULL, myP,  g);
            const float Cx = __shfl_sync(FULL, myCx, g);
            const float Cy = __shfl_sync(FULL, myCy, g);
            const u64 p2   = pk2(P,  P);
            const u64 cx2  = pk2(Cx,  Cx);
            const u64 ncx2 = pk2(-Cx, -Cx);
            const u64 cy2  = pk2(Cy,  Cy);
            const u64 ncy2 = pk2(-Cy, -Cy);
            const int pm = 1 << (8 - q);          // slot bit: 4,2,1
#pragma unroll
            for (int kk = 0; kk < 4; kk++) {
                const int lo = kk & (pm - 1);
                const int p0 = ((kk ^ lo) << 1) | lo;
                const int p1 = p0 | pm;
                const u64 ar = srp[p0], ai = sip[p0];
                const u64 dr = srp[p1], di = sip[p1];
                // n0 = P*a - C*d ; n1 = conj(C)*a + P*d
                u64 n0r = mul2(p2, ar);
                n0r = fma2(ncx2, dr, n0r); n0r = fma2(cy2,  di, n0r);
                u64 n0i = mul2(p2, ai);
                n0i = fma2(ncx2, di, n0i); n0i = fma2(ncy2, dr, n0i);
                u64 n1r = mul2(p2, dr);
                n1r = fma2(cx2,  ar, n1r); n1r = fma2(cy2,  ai, n1r);
                u64 n1i = mul2(p2, di);
                n1i = fma2(cx2,  ai, n1i); n1i = fma2(ncy2, ar, n1i);
                srp[p0] = n0r; sip[p0] = n0i;
                srp[p1] = n1r; sip[p1] = n1i;
            }
        }

        // ---- qubit 9: packed bit, gauge, vectorized via half-swap ----
        // n_r = (P,P)*v_r + (-Cx,Cx)*s_r + (Cy,Cy)*s_i
        // n_i = (P,P)*v_i + (-Cx,Cx)*s_i + (-Cy,-Cy)*s_r
        {
            const int g  = gbase + 9;
            const float P  = __shfl_sync(FULL, myP,  g);
            const float Cx = __shfl_sync(FULL, myCx, g);
            const float Cy = __shfl_sync(FULL, myCy, g);
            const u64 p2   = pk2(P,   P);
            const u64 cxp  = pk2(-Cx, Cx);
            const u64 cy2  = pk2(Cy,  Cy);
            const u64 ncy2 = pk2(-Cy, -Cy);
#pragma unroll
            for (int k = 0; k < 8; k++) {
                float ar, dr, ai, di;
                upk2(ar, dr, srp[k]);
                upk2(ai, di, sip[k]);
                const u64 swr = pk2(dr, ar);
                const u64 swi = pk2(di, ai);
                u64 nr = mul2(p2, srp[k]);
                nr = fma2(cxp, swr, nr);
                nr = fma2(cy2, swi, nr);
                u64 ni = mul2(p2, sip[k]);
                ni = fma2(cxp, swi, ni);
                ni = fma2(ncy2, swr, ni);
                srp[k] = nr; sip[k] = ni;
            }
        }

        // ---- mid CNOT chain == gray permutation new[y] = old[y ^ (y>>1)] ----
        // (after layer 1 only; layer 2's permutation folded into readout)
        // u64 shuffle first (same srcLane for both halves), then local remap.
        if (layer < 2) {
            const int srcLane = (lane ^ (lane >> 1)) ^ (w << 4);
            const bool hi = (l0 != 0);
#pragma unroll
            for (int k = 0; k < 8; k++) {
                srp[k] = __shfl_sync(FULL, srp[k], srcLane);
                sip[k] = __shfl_sync(FULL, sip[k], srcLane);
            }
            float vr[16], vi[16];
#pragma unroll
            for (int k = 0; k < 8; k++) {
                upk2(vr[2*k], vr[2*k+1], srp[k]);
                upk2(vi[2*k], vi[2*k+1], sip[k]);
            }
#pragma unroll
            for (int k = 0; k < 8; k++) {
                const int a0 = 2 * k, a1 = 2 * k + 1;
                const int c0i = (a0 >> 3) * 8 + ((((a0 >> 2) ^ (a0 >> 3)) & 1) << 2)
                              + ((((a0 >> 1) ^ (a0 >> 2)) & 1) << 1) + ((a0 ^ (a0 >> 1)) & 1);
                const int c1i = (a1 >> 3) * 8 + ((((a1 >> 2) ^ (a1 >> 3)) & 1) << 2)
                              + ((((a1 >> 1) ^ (a1 >> 2)) & 1) << 1) + ((a1 ^ (a1 >> 1)) & 1);
                const float f0r = hi ? vr[c0i ^ 8] : vr[c0i];
                const float f0i = hi ? vi[c0i ^ 8] : vi[c0i];
                const float f1r = hi ? vr[c1i ^ 8] : vr[c1i];
                const float f1i = hi ? vi[c1i ^ 8] : vi[c1i];
                srp[k] = pk2(f0r, f1r);
                sip[k] = pk2(f0i, f1i);
            }
        }
    }

    // ---- readout with folded final permutation ----
    // final[y] = S[y^(y>>1)] => sum_y |final[y]|^2 Wz(y) = sum_z |S[z]|^2 Wz(Y(z)),
    // Y_j = z9^...^z_j. Qubit q reads Y_{9-q}.
    const float w0 = head_w[0], w1 = head_w[1], w2 = head_w[2], w3 = head_w[3], w4 = head_w[4];
    const float w5 = head_w[5], w6 = head_w[6], w7 = head_w[7], w8 = head_w[8], w9 = head_w[9];
    const int c0 = w, c1 = c0 ^ l4, c2 = c1 ^ l3, c3 = c2 ^ l2, c4 = c3 ^ l1, c5 = c4 ^ l0;
    const float wl = (c0 ? -w0 : w0) + (c1 ? -w1 : w1) + (c2 ? -w2 : w2)
                   + (c3 ? -w3 : w3) + (c4 ? -w4 : w4) + (c5 ? -w5 : w5);
    const int Plane = c5;   // parity of bits 9..4; flips qubit-6..9 signs globally

    float u = 0.0f, v = 0.0f;
#pragma unroll
    for (int k = 0; k < 8; k++) {
        float r0, r1, i0, i1;
        upk2(r0, r1, srp[k]);
        upk2(i0, i1, sip[k]);
        const float p0 = r0*r0 + i0*i0;
        const float p1 = r1*r1 + i1*i1;
        const int a0 = 2*k, a1 = 2*k + 1;
        const int t3_0 = (a0 >> 3) & 1,          t2_0 = t3_0 ^ ((a0 >> 2) & 1),
                  t1_0 = t2_0 ^ ((a0 >> 1) & 1), t0_0 = t1_0 ^ (a0 & 1);
        const int t3_1 = (a1 >> 3) & 1,          t2_1 = t3_1 ^ ((a1 >> 2) & 1),
                  t1_1 = t2_1 ^ ((a1 >> 1) & 1), t0_1 = t1_1 ^ (a1 & 1);
        const float wr0 = (t3_0 ? -w6 : w6) + (t2_0 ? -w7 : w7)
                        + (t1_0 ? -w8 : w8) + (t0_0 ? -w9 : w9);
        const float wr1 = (t3_1 ? -w6 : w6) + (t2_1 ? -w7 : w7)
                        + (t1_1 ? -w8 : w8) + (t0_1 ? -w9 : w9);
        u += p0 + p1;
        v = fmaf(p0, wr0, v);
        v = fmaf(p1, wr1, v);
    }
    float part = fmaf(wl, u, Plane ? -v : v);
#pragma unroll
    for (int o = 16; o > 0; o >>= 1)
        part += __shfl_xor_sync(FULL, part, o);

    if (lane == 0) red[w] = part;
    __syncthreads();
    if (t == 0) {
        const float scale = fminf(fmaxf(logit_scale[0], 0.5f), 80.0f);
        float rr = scale * (red[0] + red[1] + head_b[0]);
        out[b] = fminf(fmaxf(rr, -30.0f), 30.0f);
    }
}

extern "C" void kernel_launch(void* const* d_in, const int* in_sizes, int n_in,
                              void* d_out, int out_size) {
    const float* x           = (const float*)d_in[0];  // (B, 49)
    const float* theta       = (const float*)d_in[1];  // (30,)
    const float* alpha_raw   = (const float*)d_in[2];  // (49,)
    const float* beta_raw    = (const float*)d_in[3];  // (49,)
    const float* head_w      = (const float*)d_in[4];  // (1,10)
    const float* head_b      = (const float*)d_in[5];  // (1,)
    const float* logit_scale = (const float*)d_in[6];  // scalar
    float* out               = (float*)d_out;          // (B,1) float32

    const int batch = in_sizes[0] / NIN;
    qcirc_kernel<<<batch, 64>>>(x, theta, alpha_raw, beta_raw,
                                head_w, head_b, logit_scale, out, batch);
}

// round 17
// speedup vs baseline: 1.0341x; 1.0341x over previous
#include <cuda_runtime.h>
#include <math.h>

#define NIN 49

typedef unsigned long long u64;

// ---- f32x2 packed helpers (sm_100+) ----
__device__ __forceinline__ u64 pk2(float lo, float hi) {
    u64 r; asm("mov.b64 %0, {%1,%2};" : "=l"(r) : "f"(lo), "f"(hi)); return r;
}
__device__ __forceinline__ void upk2(float& lo, float& hi, u64 v) {
    asm("mov.b64 {%0,%1}, %2;" : "=f"(lo), "=f"(hi) : "l"(v));
}
__device__ __forceinline__ u64 fma2(u64 a, u64 b, u64 c) {
    u64 d; asm("fma.rn.f32x2 %0, %1, %2, %3;" : "=l"(d) : "l"(a), "l"(b), "l"(c)); return d;
}
__device__ __forceinline__ u64 mul2(u64 a, u64 b) {
    u64 d; asm("mul.rn.f32x2 %0, %1, %2;" : "=l"(d) : "l"(a), "l"(b)); return d;
}

// Two warps (64 threads) = one sample. Amp index z (10 bits):
//   z9 = warp, z[8:4] = lane, z[3:1] = slot k (8 u64 SoA pairs), z0 = packed half.
// Qubit q acts on bit 9-q:
//   q0 -> warp bit (cross-warp via SMEM), q1..q5 -> lane bits (shfl butterfly),
//   q6..q8 -> slot bits (pure f32x2 FMA), q9 -> packed bit (vectorized w/ half-swap).
// Layer 0 (product state) is constructed directly with its CNOT permutation folded in.
// BOTH layers 1 and 2 use the gauge form [[P,-C],[conj(C),P]] with P real (12 FMA/pair):
//   layer 1: RIGHT gauge U' = U*H, H=diag(e^{-i psi},e^{+i psi}), psi=arg(A), C=B*A/|A|.
//     Compensation H^{-1} acts on layer-1's INPUT basis and is merged EXACTLY into the
//     layer-0 construction (thread seed + amp-coordinate doubling tree with
//     branch-constant combined factors F_j[prev][bit] = f_j(bit^prev)*c_j(bit)).
//   layer 2: LEFT gauge diag*U, C = B*conj(A)/|A|; residual per-row phases are
//     unobservable in the final |amp|^2 readout.
// Both gauge layers are FULLY UNROLLED (specialized) so ptxas can hoist layer-2's
// coefficient broadcasts into layer-1's FMA region; layer 1's exchange needs no
// leading barrier (no prior xch readers).
// The LAST layer's CNOT-chain permutation is folded into the readout weights.
__global__ void __launch_bounds__(64)
qcirc_kernel(const float* __restrict__ x,
             const float* __restrict__ theta,
             const float* __restrict__ alpha_raw,
             const float* __restrict__ beta_raw,
             const float* __restrict__ head_w,
             const float* __restrict__ head_b,
             const float* __restrict__ logit_scale,
             float* __restrict__ out, int batch)
{
    __shared__ u64 xch[16][64];     // [j<8]=re slot j, [8+j]=im slot j; col = thread
    __shared__ float red[2];

    const unsigned FULL = 0xFFFFFFFFu;
    const int t    = threadIdx.x;
    const int lane = t & 31;
    const int w    = t >> 5;
    const int b    = blockIdx.x;
    if (b >= batch) return;

    // ---- per-lane fused gate coefficients (identical in both warps) ----
    // U = RX(theta)*RY(enc) = [[A,-B],[conj(B),conj(A)]]
    // A = cx*cy - i*sx*sy,  B = cx*sy + i*sx*cy
    float myAx, myAy, myBx, myBy;   // lanes 0..9: layer-0 product factors (pure)
    float myP, myCx, myCy;          // lanes 10..29: gauge coefficients
    float myEx, myEy;               // e^{i psi} = A/|A| (used from lanes 10..19)
    {
        const int g  = (lane < 30) ? lane : 0;
        const float th = theta[g];
        const float ar = alpha_raw[g];
        const float br = beta_raw[g];
        const float xv = x[b * NIN + g];
        float sp    = fmaxf(ar, 0.0f) + log1pf(expf(-fabsf(ar)));   // softplus
        float alpha = sp + 1e-6f;
        float beta  = tanhf(br);
        const float HALF_PI = 1.5707963267948966f;                  // 0.5 * pi
        float hy = HALF_PI * (alpha * xv + beta);
        float sy, cy; sincosf(hy, &sy, &cy);
        float sx, cx; sincosf(0.5f * th, &sx, &cx);
        myAx = cx * cy;
        myAy = -sx * sy;
        myBx = cx * sy;
        myBy = sx * cy;
        const float nA = fmaxf(myAx * myAx + myAy * myAy, 1e-28f);
        const float ri = rsqrtf(nA);
        myP  = nA * ri;
        // C = B * (Ax + i*s*Ay) * ri :  s=+1 (layer-1 lanes, right gauge, uses A)
        //                               s=-1 (layer-2 lanes, left gauge, uses conj A)
        const float s   = (lane >= 10 && lane < 20) ? 1.0f : -1.0f;
        const float sAy = s * myAy;
        myCx = (myBx * myAx - myBy * sAy) * ri;
        myCy = (myBy * myAx + myBx * sAy) * ri;
        myEx = myAx * ri;
        myEy = myAy * ri;
    }

    const int l4 = (lane >> 4) & 1, l3 = (lane >> 3) & 1, l2 = (lane >> 2) & 1,
              l1 = (lane >> 1) & 1, l0 = lane & 1;

    // =====================================================================
    // Layer 0 + its CNOT chain + layer-1 gauge compensation, folded:
    //   amp[y] = comp(y) * prod_q f_q(bit_{9-q}(y ^ (y>>1)))
    //   f_q(0) = (Ax,Ay);  f_q(1) = (Bx,-By);  c_q(b) = e^{i psi_q (1-2b)}
    // permuted bits: q0<-w, q1<-l4^w, q2<-l3^l4, q3<-l2^l3, q4<-l1^l2, q5<-l0^l1,
    //   q6<-k2^l0 (l0 folded into factor swap), q7<-k1^k2, q8<-k0^k1, q9<-h^k0
    // direct bits (compensation): q0<-w, q1<-l4 .. q5<-l0, q6<-k2, q7<-k1,
    //   q8<-k0, q9<-h
    // =====================================================================
    u64 srp[8], sip[8];
    {
        const int gb[6] = { w, l4 ^ w, l3 ^ l4, l2 ^ l3, l1 ^ l2, l0 ^ l1 };
        const int cb[6] = { w, l4, l3, l2, l1, l0 };

        // thread seed (qubits 0..5): gate factor at permuted bit x comp at direct bit
        float lfr, lfi;
        {
            float Ax = __shfl_sync(FULL, myAx, 0);
            float Ay = __shfl_sync(FULL, myAy, 0);
            float Bx = __shfl_sync(FULL, myBx, 0);
            float By = __shfl_sync(FULL, myBy, 0);
            lfr = gb[0] ? Bx : Ax;
            lfi = gb[0] ? -By : Ay;
            float ex = __shfl_sync(FULL, myEx, 10);
            float ey = __shfl_sync(FULL, myEy, 10);
            float cey = cb[0] ? -ey : ey;
            float nr = lfr * ex - lfi * cey;
            float ni = lfr * cey + lfi * ex;
            lfr = nr; lfi = ni;
#pragma unroll
            for (int q = 1; q < 6; q++) {
                Ax = __shfl_sync(FULL, myAx, q);
                Ay = __shfl_sync(FULL, myAy, q);
                Bx = __shfl_sync(FULL, myBx, q);
                By = __shfl_sync(FULL, myBy, q);
                const float fr = gb[q] ? Bx : Ax;
                const float fi = gb[q] ? -By : Ay;
                nr = lfr * fr - lfi * fi;
                ni = lfr * fi + lfi * fr;
                lfr = nr; lfi = ni;
                ex = __shfl_sync(FULL, myEx, 10 + q);
                ey = __shfl_sync(FULL, myEy, 10 + q);
                cey = cb[q] ? -ey : ey;
                nr = lfr * ex - lfi * cey;
                ni = lfr * cey + lfi * ex;
                lfr = nr; lfi = ni;
            }
        }

        // combined reg factors: F[j][pb][bit] = f_{6+j}(bit^pb) * c_{6+j}(bit)
        // j=0 (bit3) has no prev bit: only [0][bit] used (f6 pre-swapped by l0).
        float Fr[4][2][2], Fi[4][2][2];
#pragma unroll
        for (int j = 0; j < 4; j++) {
            const int q = 6 + j;
            const float Ax = __shfl_sync(FULL, myAx, q);
            const float Ay = __shfl_sync(FULL, myAy, q);
            const float Bx = __shfl_sync(FULL, myBx, q);
            const float By = __shfl_sync(FULL, myBy, q);
            float f0r, f0i, f1r, f1i;
            if (j == 0) {   // f6'(v) = f6(v ^ l0)
                f0r = l0 ? Bx : Ax;  f0i = l0 ? -By : Ay;
                f1r = l0 ? Ax : Bx;  f1i = l0 ? Ay : -By;
            } else {
                f0r = Ax;  f0i = Ay;
                f1r = Bx;  f1i = -By;
            }
            const float ex = __shfl_sync(FULL, myEx, 16 + j);
            const float ey = __shfl_sync(FULL, myEy, 16 + j);
            // c(0) = (ex, ey); c(1) = (ex, -ey)
            Fr[j][0][0] = f0r * ex - f0i * ey;   Fi[j][0][0] = f0r * ey + f0i * ex;
            Fr[j][0][1] = f1r * ex + f1i * ey;   Fi[j][0][1] = -f1r * ey + f1i * ex;
            Fr[j][1][0] = f1r * ex - f1i * ey;   Fi[j][1][0] = f1r * ey + f1i * ex;
            Fr[j][1][1] = f0r * ex + f0i * ey;   Fi[j][1][1] = -f0r * ey + f0i * ex;
        }

        // doubling tree in amp coordinates a=(k2,k1,k0,h), top-down bit3->bit0.
        float gr[16], gi[16];
        gr[0] = lfr; gi[0] = lfi;
        // bit3 (j=0)
        {
            const float a_ = gr[0], c_ = gi[0];
            gr[8] = a_ * Fr[0][0][1] - c_ * Fi[0][0][1];
            gi[8] = a_ * Fi[0][0][1] + c_ * Fr[0][0][1];
            gr[0] = a_ * Fr[0][0][0] - c_ * Fi[0][0][0];
            gi[0] = a_ * Fi[0][0][0] + c_ * Fr[0][0][0];
        }
        // bit2 (j=1)
#pragma unroll
        for (int c0 = 0; c0 < 16; c0 += 8) {
            const int pb = c0 >> 3;
            const float a_ = gr[c0], c_ = gi[c0];
            gr[c0 + 4] = a_ * Fr[1][pb][1] - c_ * Fi[1][pb][1];
            gi[c0 + 4] = a_ * Fi[1][pb][1] + c_ * Fr[1][pb][1];
            gr[c0]     = a_ * Fr[1][pb][0] - c_ * Fi[1][pb][0];
            gi[c0]     = a_ * Fi[1][pb][0] + c_ * Fr[1][pb][0];
        }
        // bit1 (j=2)
#pragma unroll
        for (int c0 = 0; c0 < 16; c0 += 4) {
            const int pb = (c0 >> 2) & 1;
            const float a_ = gr[c0], c_ = gi[c0];
            gr[c0 + 2] = a_ * Fr[2][pb][1] - c_ * Fi[2][pb][1];
            gi[c0 + 2] = a_ * Fi[2][pb][1] + c_ * Fr[2][pb][1];
            gr[c0]     = a_ * Fr[2][pb][0] - c_ * Fi[2][pb][0];
            gi[c0]     = a_ * Fi[2][pb][0] + c_ * Fr[2][pb][0];
        }
        // bit0 (j=3)
#pragma unroll
        for (int c0 = 0; c0 < 16; c0 += 2) {
            const int pb = (c0 >> 1) & 1;
            const float a_ = gr[c0], c_ = gi[c0];
            gr[c0 + 1] = a_ * Fr[3][pb][1] - c_ * Fi[3][pb][1];
            gi[c0 + 1] = a_ * Fi[3][pb][1] + c_ * Fr[3][pb][1];
            gr[c0]     = a_ * Fr[3][pb][0] - c_ * Fi[3][pb][0];
            gi[c0]     = a_ * Fi[3][pb][0] + c_ * Fr[3][pb][0];
        }

        // pack directly (no renaming: tree already in amp coordinates)
#pragma unroll
        for (int k = 0; k < 8; k++) {
            srp[k] = pk2(gr[2 * k], gr[2 * k + 1]);
            sip[k] = pk2(gi[2 * k], gi[2 * k + 1]);
        }
    }

    // =====================================================================
    // Gauge layer body (layers 1 and 2), fully specialized via lambda.
    // =====================================================================
    auto gauge_layer = [&](const int gbase, const bool firstLayer) {
        // ---- qubit 0: cross-warp gauge gate via SMEM exchange ----
        {
            if (!firstLayer) __syncthreads();   // prior readers of xch done
#pragma unroll
            for (int j = 0; j < 8; j++) {
                xch[j][t]     = srp[j];
                xch[j + 8][t] = sip[j];
            }
            __syncthreads();

            const float P  = __shfl_sync(FULL, myP,  gbase);
            const float Cx = __shfl_sync(FULL, myCx, gbase);
            const float Cy = __shfl_sync(FULL, myCy, gbase);
            const bool hi = (w != 0);
            const float Dx = hi ? Cx : -Cx;
            const u64 p2   = pk2(P,  P);
            const u64 dx2  = pk2(Dx, Dx);
            const u64 cy2  = pk2(Cy, Cy);
            const u64 ncy2 = pk2(-Cy, -Cy);
            const int pt = t ^ 32;
            u64 prp[8], pip[8];
#pragma unroll
            for (int k = 0; k < 8; k++) {
                prp[k] = xch[k][pt];
                pip[k] = xch[k + 8][pt];
            }
#pragma unroll
            for (int k = 0; k < 8; k++) {
                u64 nr = mul2(p2, srp[k]);
                nr = fma2(dx2, prp[k], nr);
                nr = fma2(cy2, pip[k], nr);
                u64 ni = mul2(p2, sip[k]);
                ni = fma2(dx2, pip[k], ni);
                ni = fma2(ncy2, prp[k], ni);
                srp[k] = nr; sip[k] = ni;
            }
        }

        // ---- qubits 1..5: lane-bit gauge gates, two-phase ----
#pragma unroll
        for (int q = 1; q < 6; q++) {
            const int g  = gbase + q;
            const float P  = __shfl_sync(FULL, myP,  g);
            const float Cx = __shfl_sync(FULL, myCx, g);
            const float Cy = __shfl_sync(FULL, myCy, g);
            const int m = 1 << (5 - q);
            const bool hi = (lane & m) != 0;
            const float Dx = hi ? Cx : -Cx;
            const u64 p2   = pk2(P,  P);
            const u64 dx2  = pk2(Dx, Dx);
            const u64 cy2  = pk2(Cy, Cy);
            const u64 ncy2 = pk2(-Cy, -Cy);
            u64 prp[8], pip[8];
#pragma unroll
            for (int k = 0; k < 8; k++) {
                float r0, r1, i0, i1;
                upk2(r0, r1, srp[k]);
                upk2(i0, i1, sip[k]);
                const float pr0 = __shfl_xor_sync(FULL, r0, m);
                const float pr1 = __shfl_xor_sync(FULL, r1, m);
                const float pi0 = __shfl_xor_sync(FULL, i0, m);
                const float pi1 = __shfl_xor_sync(FULL, i1, m);
                prp[k] = pk2(pr0, pr1);
                pip[k] = pk2(pi0, pi1);
            }
#pragma unroll
            for (int k = 0; k < 8; k++) {
                u64 nr = mul2(p2, srp[k]);
                nr = fma2(dx2, prp[k], nr);
                nr = fma2(cy2, pip[k], nr);
                u64 ni = mul2(p2, sip[k]);
                ni = fma2(dx2, pip[k], ni);
                ni = fma2(ncy2, prp[k], ni);
                srp[k] = nr; sip[k] = ni;
            }
        }

        // ---- qubits 6..8: slot-bit gauge gates ----
#pragma unroll
        for (int q = 6; q < 9; q++) {
            const int g  = gbase + q;
            const float P  = __shfl_sync(FULL, myP,  g);
            const float Cx = __shfl_sync(FULL, myCx, g);
            const float Cy = __shfl_sync(FULL, myCy, g);
            const u64 p2   = pk2(P,  P);
            const u64 cx2  = pk2(Cx,  Cx);
            const u64 ncx2 = pk2(-Cx, -Cx);
            const u64 cy2  = pk2(Cy,  Cy);
            const u64 ncy2 = pk2(-Cy, -Cy);
            const int pm = 1 << (8 - q);          // slot bit: 4,2,1
#pragma unroll
            for (int kk = 0; kk < 4; kk++) {
                const int lo = kk & (pm - 1);
                const int p0 = ((kk ^ lo) << 1) | lo;
                const int p1 = p0 | pm;
                const u64 ar = srp[p0], ai = sip[p0];
                const u64 dr = srp[p1], di = sip[p1];
                // n0 = P*a - C*d ; n1 = conj(C)*a + P*d
                u64 n0r = mul2(p2, ar);
                n0r = fma2(ncx2, dr, n0r); n0r = fma2(cy2,  di, n0r);
                u64 n0i = mul2(p2, ai);
                n0i = fma2(ncx2, di, n0i); n0i = fma2(ncy2, dr, n0i);
                u64 n1r = mul2(p2, dr);
                n1r = fma2(cx2,  ar, n1r); n1r = fma2(cy2,  ai, n1r);
                u64 n1i = mul2(p2, di);
                n1i = fma2(cx2,  ai, n1i); n1i = fma2(ncy2, ar, n1i);
                srp[p0] = n0r; sip[p0] = n0i;
                srp[p1] = n1r; sip[p1] = n1i;
            }
        }

        // ---- qubit 9: packed bit, gauge, vectorized via half-swap ----
        // n_r = (P,P)*v_r + (-Cx,Cx)*s_r + (Cy,Cy)*s_i
        // n_i = (P,P)*v_i + (-Cx,Cx)*s_i + (-Cy,-Cy)*s_r
        {
            const int g  = gbase + 9;
            const float P  = __shfl_sync(FULL, myP,  g);
            const float Cx = __shfl_sync(FULL, myCx, g);
            const float Cy = __shfl_sync(FULL, myCy, g);
            const u64 p2   = pk2(P,   P);
            const u64 cxp  = pk2(-Cx, Cx);
            const u64 cy2  = pk2(Cy,  Cy);
            const u64 ncy2 = pk2(-Cy, -Cy);
#pragma unroll
            for (int k = 0; k < 8; k++) {
                float ar, dr, ai, di;
                upk2(ar, dr, srp[k]);
                upk2(ai, di, sip[k]);
                const u64 swr = pk2(dr, ar);
                const u64 swi = pk2(di, ai);
                u64 nr = mul2(p2, srp[k]);
                nr = fma2(cxp, swr, nr);
                nr = fma2(cy2, swi, nr);
                u64 ni = mul2(p2, sip[k]);
                ni = fma2(cxp, swi, ni);
                ni = fma2(ncy2, swr, ni);
                srp[k] = nr; sip[k] = ni;
            }
        }

        // ---- mid CNOT chain == gray permutation new[y] = old[y ^ (y>>1)] ----
        // (after layer 1 only; layer 2's permutation folded into readout)
        if (firstLayer) {
            float vr[16], vi[16];
#pragma unroll
            for (int k = 0; k < 8; k++) {
                upk2(vr[2*k], vr[2*k+1], srp[k]);
                upk2(vi[2*k], vi[2*k+1], sip[k]);
            }
            const int srcLane = (lane ^ (lane >> 1)) ^ (w << 4);
            const bool hi = (l0 != 0);
#pragma unroll
            for (int j = 0; j < 16; j++) {
                vr[j] = __shfl_sync(FULL, vr[j], srcLane);
                vi[j] = __shfl_sync(FULL, vi[j], srcLane);
            }
#pragma unroll
            for (int k = 0; k < 8; k++) {
                const int a0 = 2 * k, a1 = 2 * k + 1;
                const int c0i = (a0 >> 3) * 8 + ((((a0 >> 2) ^ (a0 >> 3)) & 1) << 2)
                              + ((((a0 >> 1) ^ (a0 >> 2)) & 1) << 1) + ((a0 ^ (a0 >> 1)) & 1);
                const int c1i = (a1 >> 3) * 8 + ((((a1 >> 2) ^ (a1 >> 3)) & 1) << 2)
                              + ((((a1 >> 1) ^ (a1 >> 2)) & 1) << 1) + ((a1 ^ (a1 >> 1)) & 1);
                const float f0r = hi ? vr[c0i ^ 8] : vr[c0i];
                const float f0i = hi ? vi[c0i ^ 8] : vi[c0i];
                const float f1r = hi ? vr[c1i ^ 8] : vr[c1i];
                const float f1i = hi ? vi[c1i ^ 8] : vi[c1i];
                srp[k] = pk2(f0r, f1r);
                sip[k] = pk2(f0i, f1i);
            }
        }
    };

    gauge_layer(10, true);
    gauge_layer(20, false);

    // ---- readout with folded final permutation ----
    // final[y] = S[y^(y>>1)] => sum_y |final[y]|^2 Wz(y) = sum_z |S[z]|^2 Wz(Y(z)),
    // Y_j = z9^...^z_j. Qubit q reads Y_{9-q}.
    const float w0 = head_w[0], w1 = head_w[1], w2 = head_w[2], w3 = head_w[3], w4 = head_w[4];
    const float w5 = head_w[5], w6 = head_w[6], w7 = head_w[7], w8 = head_w[8], w9 = head_w[9];
    const int c0 = w, c1 = c0 ^ l4, c2 = c1 ^ l3, c3 = c2 ^ l2, c4 = c3 ^ l1, c5 = c4 ^ l0;
    const float wl = (c0 ? -w0 : w0) + (c1 ? -w1 : w1) + (c2 ? -w2 : w2)
                   + (c3 ? -w3 : w3) + (c4 ? -w4 : w4) + (c5 ? -w5 : w5);
    const int Plane = c5;   // parity of bits 9..4; flips qubit-6..9 signs globally

    float u = 0.0f, v = 0.0f;
#pragma unroll
    for (int k = 0; k < 8; k++) {
        float r0, r1, i0, i1;
        upk2(r0, r1, srp[k]);
        upk2(i0, i1, sip[k]);
        const float p0 = r0*r0 + i0*i0;
        const float p1 = r1*r1 + i1*i1;
        const int a0 = 2*k, a1 = 2*k + 1;
        const int t3_0 = (a0 >> 3) & 1,          t2_0 = t3_0 ^ ((a0 >> 2) & 1),
                  t1_0 = t2_0 ^ ((a0 >> 1) & 1), t0_0 = t1_0 ^ (a0 & 1);
        const int t3_1 = (a1 >> 3) & 1,          t2_1 = t3_1 ^ ((a1 >> 2) & 1),
                  t1_1 = t2_1 ^ ((a1 >> 1) & 1), t0_1 = t1_1 ^ (a1 & 1);
        const float wr0 = (t3_0 ? -w6 : w6) + (t2_0 ? -w7 : w7)
                        + (t1_0 ? -w8 : w8) + (t0_0 ? -w9 : w9);
        const float wr1 = (t3_1 ? -w6 : w6) + (t2_1 ? -w7 : w7)
                        + (t1_1 ? -w8 : w8) + (t0_1 ? -w9 : w9);
        u += p0 + p1;
        v = fmaf(p0, wr0, v);
        v = fmaf(p1, wr1, v);
    }
    float part = fmaf(wl, u, Plane ? -v : v);
#pragma unroll
    for (int o = 16; o > 0; o >>= 1)
        part += __shfl_xor_sync(FULL, part, o);

    if (lane == 0) red[w] = part;
    __syncthreads();
    if (t == 0) {
        const float scale = fminf(fmaxf(logit_scale[0], 0.5f), 80.0f);
        float rr = scale * (red[0] + red[1] + head_b[0]);
        out[b] = fminf(fmaxf(rr, -30.0f), 30.0f);
    }
}

extern "C" void kernel_launch(void* const* d_in, const int* in_sizes, int n_in,
                              void* d_out, int out_size) {
    const float* x           = (const float*)d_in[0];  // (B, 49)
    const float* theta       = (const float*)d_in[1];  // (30,)
    const float* alpha_raw   = (const float*)d_in[2];  // (49,)
    const float* beta_raw    = (const float*)d_in[3];  // (49,)
    const float* head_w      = (const float*)d_in[4];  // (1,10)
    const float* head_b      = (const float*)d_in[5];  // (1,)
    const float* logit_scale = (const float*)d_in[6];  // scalar
    float* out               = (float*)d_out;          // (B,1) float32

    const int batch = in_sizes[0] / NIN;
    qcirc_kernel<<<batch, 64>>>(x, theta, alpha_raw, beta_raw,
                                head_w, head_b, logit_scale, out, batch);
}